// round 16
// baseline (speedup 1.0000x reference)
#include <cuda_runtime.h>
#include <cuda.h>
#include <cuda_bf16.h>
#include <cstdint>

#define NTOK   8192
#define DIM    1024
#define NEXP   8
#define CAP    1024
#define LN_EPS 1e-5f

#if defined(__CUDA_ARCH_FEAT_SM103_ALL) || defined(__CUDA_ARCH_FEAT_SM100_ALL)
#define HAS_TCGEN05 1
#else
#define HAS_TCGEN05 0
#endif

// ---------------- scratch (device globals: no allocation) -------------------
__device__ float g_wt[NEXP * DIM * DIM];   // W transposed: [e][n][k], fp32
__device__ float g_h [NTOK * DIM];

// ---------------- PTX helpers (guarded) -------------------------------------
#if HAS_TCGEN05
__device__ __forceinline__ uint32_t smem_u32(const void* p) {
    uint32_t a;
    asm("{ .reg .u64 t; cvta.to.shared.u64 t, %1; cvt.u32.u64 %0, t; }" : "=r"(a) : "l"(p));
    return a;
}
__device__ __forceinline__ uint32_t elect_one_pred() {
    uint32_t p;
    asm volatile("{\n\t.reg .pred p;\n\telect.sync _|p, 0xFFFFFFFF;\n\tselp.b32 %0, 1, 0, p;\n\t}" : "=r"(p));
    return p;
}
__device__ __forceinline__ uint32_t cluster_rank() {
    uint32_t r;
    asm("mov.u32 %0, %%cluster_ctarank;" : "=r"(r));
    return r;
}

#define MBARRIER_INIT(addr, cnt) \
    asm volatile("mbarrier.init.shared.b64 [%0], %1;" :: "r"(addr), "r"(cnt) : "memory")
#define MBARRIER_INVAL(addr) \
    asm volatile("mbarrier.inval.shared.b64 [%0];" :: "r"(addr) : "memory")
#define MBARRIER_EXPECT_TX(addr, bytes) \
    asm volatile("mbarrier.arrive.expect_tx.shared.b64 _, [%0], %1;" :: "r"(addr), "r"(bytes) : "memory")
#define MBARRIER_ARRIVE_RANK(local_addr, target_rank) \
    asm volatile("{\n\t.reg .b32 ra;\n\t" \
        "mapa.shared::cluster.u32 ra, %0, %1;\n\t" \
        "mbarrier.arrive.shared::cluster.b64 _, [ra];\n\t}" \
        :: "r"(local_addr), "r"(target_rank) : "memory")
#define MBARRIER_WAIT_PARITY(addr, par) do {                                        \
    uint32_t _m = (addr), _p = (par), _d;                                           \
    asm volatile("{\n\t.reg .pred p;\n\t"                                           \
        "mbarrier.try_wait.parity.acquire.cta.shared::cta.b64 p, [%1], %2;\n\t"     \
        "selp.b32 %0, 1, 0, p;\n\t}" : "=r"(_d) : "r"(_m), "r"(_p) : "memory");     \
    if (!_d) {                                                                      \
        asm volatile("{\n\t.reg .pred P1;\n\t"                                      \
            "WL_%=:\n\t"                                                            \
            "mbarrier.try_wait.parity.acquire.cta.shared::cta.b64 P1, [%0], %1, 0x989680;\n\t" \
            "@P1 bra.uni WD_%=;\n\tbra.uni WL_%=;\n\tWD_%=:\n\t}"                   \
            :: "r"(_m), "r"(_p) : "memory");                                        \
    } } while (0)

#define TMA_LOAD_2D(smem_addr, map, cx, cy, mbar) \
    asm volatile("cp.async.bulk.tensor.2d.shared::cta.global.tile.mbarrier::complete_tx::bytes " \
        "[%0], [%1, {%2, %3}], [%4];" \
        :: "r"(smem_addr), "l"(map), "r"(cx), "r"(cy), "r"(mbar) : "memory")

#define CLUSTER_SYNC() do { \
    asm volatile("barrier.cluster.arrive.aligned;" ::: "memory"); \
    asm volatile("barrier.cluster.wait.aligned;"   ::: "memory"); } while (0)

#define TCGEN05_ALLOC_CG2(smem_addr, ncols) \
    asm volatile("tcgen05.alloc.cta_group::2.sync.aligned.shared::cta.b32 [%0], %1;" \
                 :: "r"(smem_addr), "r"(ncols) : "memory")
#define TCGEN05_DEALLOC_CG2(tmem, ncols) \
    asm volatile("tcgen05.dealloc.cta_group::2.sync.aligned.b32 %0, %1;" :: "r"(tmem), "r"(ncols))
#define TCGEN05_RELINQ_CG2() \
    asm volatile("tcgen05.relinquish_alloc_permit.cta_group::2.sync.aligned;")
#define TCGEN05_COMMIT_MC_CG2(mbar, mask) \
    asm volatile("tcgen05.commit.cta_group::2.mbarrier::arrive::one.shared::cluster.multicast::cluster.b64 [%0], %1;" \
                 :: "r"(mbar), "h"((uint16_t)(mask)) : "memory")
#define TCGEN05_FENCE_AFTER() \
    asm volatile("tcgen05.fence::after_thread_sync;" ::: "memory")
#define TCGEN05_FENCE_BEFORE() \
    asm volatile("tcgen05.fence::before_thread_sync;" ::: "memory")
#define TCGEN05_WAIT_LD() \
    asm volatile("tcgen05.wait::ld.sync.aligned;" ::: "memory")

#define TCGEN05_LD_X32(r, tmem_addr) \
    asm volatile("tcgen05.ld.sync.aligned.32x32b.x32.b32 " \
        "{%0, %1, %2, %3, %4, %5, %6, %7, %8, %9, %10, %11, %12, %13, %14, %15, " \
        " %16, %17, %18, %19, %20, %21, %22, %23, %24, %25, %26, %27, %28, %29, %30, %31}, [%32];" \
        : "=r"((r)[0]),  "=r"((r)[1]),  "=r"((r)[2]),  "=r"((r)[3]),  \
          "=r"((r)[4]),  "=r"((r)[5]),  "=r"((r)[6]),  "=r"((r)[7]),  \
          "=r"((r)[8]),  "=r"((r)[9]),  "=r"((r)[10]), "=r"((r)[11]), \
          "=r"((r)[12]), "=r"((r)[13]), "=r"((r)[14]), "=r"((r)[15]), \
          "=r"((r)[16]), "=r"((r)[17]), "=r"((r)[18]), "=r"((r)[19]), \
          "=r"((r)[20]), "=r"((r)[21]), "=r"((r)[22]), "=r"((r)[23]), \
          "=r"((r)[24]), "=r"((r)[25]), "=r"((r)[26]), "=r"((r)[27]), \
          "=r"((r)[28]), "=r"((r)[29]), "=r"((r)[30]), "=r"((r)[31]) \
        : "r"(tmem_addr))

// cg2 SS tf32 MMA: M=256 across the pair, fp32 accum in TMEM (K=8 per step).
__device__ __forceinline__ void mma_tf32_ss_cg2(uint32_t d_tmem, uint64_t a_desc,
                                                uint64_t b_desc, uint32_t idesc, bool acc) {
    uint32_t en = acc ? 1u : 0u, z = 0u;
    asm volatile("{\n\t.reg .pred p;\n\tsetp.ne.u32 p, %6, 0;\n\t"
        "tcgen05.mma.cta_group::2.kind::tf32 [%0], %1, %2, %3, "
        "{%4, %4, %4, %4, %4, %4, %4, %4}, p;\n\t}"
        :: "r"(d_tmem), "l"(a_desc), "l"(b_desc), "r"(idesc),
           "r"(z), "r"(z), "r"(en) : "memory");
}

// SW64 K-major descriptor (layout=4, version=1, SBO=32, LBO=1) — proven R6/R7/R11.
static __device__ __forceinline__ uint64_t make_desc_sw64(uint32_t addr) {
    const uint64_t BASE = (4ull << 61) | (1ull << 46) | (32ull << 32) | (1ull << 16);
    return BASE | ((uint64_t)(addr >> 4) & 0x3FFFull);
}

// idesc: dtype F32, a/b TF32, N=256, M_TOTAL=256 (cg2, as in test_2cta_mma_bf16)
#define MMA_IDESC ((1u << 4) | (2u << 7) | (2u << 10) | ((256u / 8) << 17) | ((256u / 16) << 24))
#endif // HAS_TCGEN05

// ---------------------------------------------------------------------------
// W transpose (fp32): 64x64 tile per CTA (R11 version, measured 12.6us).
// ---------------------------------------------------------------------------
__global__ __launch_bounds__(256)
void transpose_w_kernel(const float* __restrict__ W, float* __restrict__ Wt)
{
    __shared__ float t[64][65];
    const int e  = blockIdx.z;
    const int k0 = blockIdx.y * 64;
    const int n0 = blockIdx.x * 64;
    const int tid = threadIdx.x;
    const int rr  = tid >> 4;
    const int c4  = tid & 15;

    const float* Wp = W + (size_t)e * DIM * DIM;
    #pragma unroll
    for (int i = 0; i < 4; ++i) {
        int row = rr + i * 16;
        float4 v = *(const float4*)(Wp + (size_t)(k0 + row) * DIM + n0 + c4 * 4);
        t[row][c4 * 4 + 0] = v.x;
        t[row][c4 * 4 + 1] = v.y;
        t[row][c4 * 4 + 2] = v.z;
        t[row][c4 * 4 + 3] = v.w;
    }
    __syncthreads();

    float* Wtp = Wt + (size_t)e * DIM * DIM;
    #pragma unroll
    for (int i = 0; i < 4; ++i) {
        int n = rr + i * 16;
        float4 v;
        v.x = t[c4 * 4 + 0][n];
        v.y = t[c4 * 4 + 1][n];
        v.z = t[c4 * 4 + 2][n];
        v.w = t[c4 * 4 + 3][n];
        *(float4*)(Wtp + (size_t)(n0 + n) * DIM + k0 + c4 * 4) = v;
    }
}

// ---------------------------------------------------------------------------
// GEMM: tf32 cta_group::2, cluster (2,1,1) ALONG X (proven cg2 shape).
// Pair = blockIdx.x>>1 -> one M=256 x N=256 tile; rank = blockIdx.x&1 picks
// the M-half (A rows) and the B-half (cg2 B-split). Leader issues M256
// dispatches; peer remote-arrives leader's full barrier after its TMA lands.
// ---------------------------------------------------------------------------
#define NSTAGE      6
#define K_CHUNK     16
#define N_CHUNKS    64               // 1024 / 16
#define STAGE_BYTES 16384            // A-half 8K (128r x 64B) + B-half 8K
#define ST_A 0
#define ST_B 8192
#define OFF_BIAS  (NSTAGE * STAGE_BYTES)       // 98304, 1KB
#define OFF_TPTR  (OFF_BIAS + 1024)            // 16B
#define OFF_FULL  (OFF_TPTR + 16)              // 6 x 8B
#define OFF_EMPTY (OFF_FULL + 48)              // 6 x 8B
#define OFF_FINAL (OFF_EMPTY + 48)
#define SMEM_SIZE (OFF_FINAL + 16)

__global__ __launch_bounds__(256, 2) __cluster_dims__(2, 1, 1)
void gemm_tc_kernel(const __grid_constant__ CUtensorMap tmX,
                    const __grid_constant__ CUtensorMap tmW,
                    const float* __restrict__ X,
                    const float* __restrict__ Wt,
                    const float* __restrict__ bias,
                    float* __restrict__ H)
{
#if HAS_TCGEN05
    extern __shared__ __align__(1024) char smem[];
    const uint32_t sbase  = smem_u32(smem);
    const int e      = blockIdx.z;
    const int tile_m = (blockIdx.x >> 1) * 256;   // pair's M tile
    const int tile_n = blockIdx.y * 256;
    const uint32_t rank = cluster_rank();         // 0 = leader, = blockIdx.x&1
    const int mrow0  = tile_m + (int)rank * 128;  // this CTA's 128 M-rows
    const int tid    = threadIdx.x;
    const int wid    = tid >> 5;
    const int lid    = tid & 31;

    if (wid == 0) {
        TCGEN05_ALLOC_CG2(sbase + OFF_TPTR, 256);
        TCGEN05_RELINQ_CG2();
    }
    if (tid == 0) {
        #pragma unroll
        for (int s = 0; s < NSTAGE; ++s) {
            // leader full: local expect_tx-arrive + peer remote-arrive = 2
            MBARRIER_INIT(sbase + OFF_FULL  + s * 8, (rank == 0) ? 2u : 1u);
            MBARRIER_INIT(sbase + OFF_EMPTY + s * 8, 1);   // one cg2 commit-MC
        }
        MBARRIER_INIT(sbase + OFF_FINAL, 1);
    }
    ((float*)(smem + OFF_BIAS))[tid] = bias[e * DIM + tile_n + tid];
    __syncthreads();
    CLUSTER_SYNC();                 // peer barriers live before remote arrives/commits
    uint32_t tmem;
    asm volatile("ld.shared.b32 %0, [%1];" : "=r"(tmem) : "r"(sbase + OFF_TPTR));

    if (tid == 0) {
        // ------- producer: this CTA's A-half + B-half per chunk
        const int rowA = e * CAP + mrow0;                    // X rows (128-row box)
        const int rowB = e * DIM + tile_n + (int)rank * 128; // Wt rows (B split half)
        int st = 0, it = 0;
        for (int c = 0; c < N_CHUNKS; ++c) {
            if (c >= NSTAGE)
                MBARRIER_WAIT_PARITY(sbase + OFF_EMPTY + st * 8, (it - 1) & 1);
            const uint32_t bb = sbase + st * STAGE_BYTES;
            const uint32_t fb = sbase + OFF_FULL + st * 8;
            const int cx = c * K_CHUNK;
            MBARRIER_EXPECT_TX(fb, STAGE_BYTES);             // local 16K
            TMA_LOAD_2D(bb + ST_A, &tmX, cx, rowA, fb);
            TMA_LOAD_2D(bb + ST_B, &tmW, cx, rowB, fb);
            if (rank != 0) {
                // wait local tx complete, then signal leader's full barrier
                MBARRIER_WAIT_PARITY(fb, it & 1);
                MBARRIER_ARRIVE_RANK(fb, 0);
            }
            if (++st == NSTAGE) { st = 0; ++it; }
        }
    } else if (wid == 1 && rank == 0) {
        // ---------------- MMA warp (leader CTA, single elected thread)
        if (elect_one_pred()) {
            int st = 0, it = 0;
            for (int c = 0; c < N_CHUNKS; ++c) {
                MBARRIER_WAIT_PARITY(sbase + OFF_FULL + st * 8, it & 1);
                const uint32_t bb = sbase + st * STAGE_BYTES;
                uint64_t dA = make_desc_sw64(bb + ST_A);     // M=256 via both CTAs
                uint64_t dB = make_desc_sw64(bb + ST_B);     // N split across pair
                #pragma unroll
                for (int kk = 0; kk < 2; ++kk)               // K=8 steps (+2 units = 32B)
                    mma_tf32_ss_cg2(tmem, dA + kk * 2, dB + kk * 2, MMA_IDESC,
                                    !(c == 0 && kk == 0));
                TCGEN05_COMMIT_MC_CG2(sbase + OFF_EMPTY + st * 8, 0x3);
                if (++st == NSTAGE) { st = 0; ++it; }
            }
            TCGEN05_COMMIT_MC_CG2(sbase + OFF_FINAL, 0x3);
        }
    }

    // ---------------- epilogue: each CTA reads its 128-lane x 256-col D half
    MBARRIER_WAIT_PARITY(sbase + OFF_FINAL, 0);
    TCGEN05_FENCE_AFTER();

    {
        const int half = wid >> 2, sub = wid & 3;            // col half, row group
        const int row  = mrow0 + sub * 32 + lid;             // global M row
        float* outp = H + (size_t)(e * CAP + row) * DIM + tile_n + half * 128;
        const float* bs = (const float*)(smem + OFF_BIAS) + half * 128;
        const uint32_t dbase = tmem + half * 128;
        #pragma unroll
        for (int base = 0; base < 128; base += 32) {
            uint32_t r[32];
            TCGEN05_LD_X32(r, dbase + base);
            TCGEN05_WAIT_LD();
            float v[32];
            #pragma unroll
            for (int i = 0; i < 32; ++i)
                v[i] = fmaxf(__uint_as_float(r[i]) + bs[base + i], 0.f);
            #pragma unroll
            for (int q = 0; q < 8; ++q)
                *(float4*)(outp + base + q * 4) = *(float4*)&v[q * 4];
        }
        TCGEN05_FENCE_BEFORE();
    }
    __syncthreads();
    if (tid == 0) {
        #pragma unroll
        for (int s = 0; s < NSTAGE; ++s) {
            MBARRIER_INVAL(sbase + OFF_FULL  + s * 8);
            MBARRIER_INVAL(sbase + OFF_EMPTY + s * 8);
        }
        MBARRIER_INVAL(sbase + OFF_FINAL);
    }
    __syncthreads();
    if (wid == 0) TCGEN05_DEALLOC_CG2(tmem, 256);
    CLUSTER_SYNC();                 // no CTA exits while peer ops may target it

#else
    // ---------------- trivial correct fallback (family-level image; not used on GB300)
    const int e      = blockIdx.z;
    const int tile_m = (blockIdx.x >> 1) * 256;
    const int tile_n = blockIdx.y * 256;
    const int mrow0  = tile_m + (blockIdx.x & 1) * 128;
    const int tid    = threadIdx.x;
    if (tid < 128) {
        const int row = mrow0 + tid;
        const float* Ap = X + (size_t)(e * CAP + row) * DIM;
        for (int n = 0; n < 256; ++n) {
            const float* Bp = Wt + ((size_t)e * DIM + tile_n + n) * DIM;
            float s = 0.f;
            for (int k = 0; k < DIM; ++k) s = fmaf(Ap[k], Bp[k], s);
            s += bias[e * DIM + tile_n + n];
            H[(size_t)(e * CAP + row) * DIM + tile_n + n] = fmaxf(s, 0.f);
        }
    }
#endif
}

// ---------------------------------------------------------------------------
// LayerNorm over D=1024 per row; one 256-thread CTA per token. (R3 version)
// ---------------------------------------------------------------------------
__global__ __launch_bounds__(256)
void layernorm_kernel(const float* __restrict__ H,
                      const float* __restrict__ gamma,
                      const float* __restrict__ beta,
                      float* __restrict__ out)
{
    const int row = blockIdx.x;
    const int e   = row >> 10;
    const int tid = threadIdx.x;

    const float* h = H + (size_t)row * DIM;
    float4 v = *(const float4*)(h + tid * 4);

    float s  = v.x + v.y + v.z + v.w;
    float sq = v.x * v.x + v.y * v.y + v.z * v.z + v.w * v.w;

    #pragma unroll
    for (int off = 16; off > 0; off >>= 1) {
        s  += __shfl_xor_sync(0xffffffffu, s,  off);
        sq += __shfl_xor_sync(0xffffffffu, sq, off);
    }

    __shared__ float red_s[8], red_q[8];
    const int wid = tid >> 5, lid = tid & 31;
    if (lid == 0) { red_s[wid] = s; red_q[wid] = sq; }
    __syncthreads();

    __shared__ float s_mean, s_rstd;
    if (wid == 0) {
        float ts = (lid < 8) ? red_s[lid] : 0.f;
        float tq = (lid < 8) ? red_q[lid] : 0.f;
        #pragma unroll
        for (int off = 4; off > 0; off >>= 1) {
            ts += __shfl_xor_sync(0xffffffffu, ts, off);
            tq += __shfl_xor_sync(0xffffffffu, tq, off);
        }
        if (lid == 0) {
            float mean = ts * (1.f / DIM);
            float var  = tq * (1.f / DIM) - mean * mean;
            s_mean = mean;
            s_rstd = rsqrtf(var + LN_EPS);
        }
    }
    __syncthreads();

    const float mean = s_mean, rstd = s_rstd;
    float4 g  = *(const float4*)(gamma + (size_t)e * DIM + tid * 4);
    float4 bt = *(const float4*)(beta  + (size_t)e * DIM + tid * 4);

    float4 o;
    o.x = (v.x - mean) * rstd * g.x + bt.x;
    o.y = (v.y - mean) * rstd * g.y + bt.y;
    o.z = (v.z - mean) * rstd * g.z + bt.z;
    o.w = (v.w - mean) * rstd * g.w + bt.w;
    *(float4*)(out + (size_t)row * DIM + tid * 4) = o;
}

// ---------------------------------------------------------------------------
typedef CUresult (CUDAAPI *pfn_encode_t)(
    CUtensorMap*, CUtensorMapDataType, cuuint32_t, void*,
    const cuuint64_t*, const cuuint64_t*, const cuuint32_t*, const cuuint32_t*,
    CUtensorMapInterleave, CUtensorMapSwizzle, CUtensorMapL2promotion,
    CUtensorMapFloatOOBfill);

static void encode_map_f32(pfn_encode_t fn, CUtensorMap* tm, void* ptr, int nrows)
{
    cuuint64_t dims[2]    = {(cuuint64_t)DIM, (cuuint64_t)nrows};
    cuuint64_t strides[1] = {(cuuint64_t)(DIM * 4)};   // bytes per row (f32)
    cuuint32_t box[2]     = {16, 128};                 // 64B x 128 rows, SW64
    cuuint32_t estr[2]    = {1, 1};
    fn(tm, CU_TENSOR_MAP_DATA_TYPE_FLOAT32, 2, ptr, dims, strides, box, estr,
       CU_TENSOR_MAP_INTERLEAVE_NONE, CU_TENSOR_MAP_SWIZZLE_64B,
       CU_TENSOR_MAP_L2_PROMOTION_L2_128B, CU_TENSOR_MAP_FLOAT_OOB_FILL_NONE);
}

extern "C" void kernel_launch(void* const* d_in, const int* in_sizes, int n_in,
                              void* d_out, int out_size)
{
    const float* x     = (const float*)d_in[0];
    // d_in[1] = expert_frequency (equal capacities) — unused
    const float* W     = (const float*)d_in[2];
    const float* bias  = (const float*)d_in[3];
    const float* gamma = (const float*)d_in[4];
    const float* beta  = (const float*)d_in[5];
    float*       out   = (float*)d_out;

    float *wt, *h;
    cudaGetSymbolAddress((void**)&wt, g_wt);
    cudaGetSymbolAddress((void**)&h,  g_h);

    static bool init_done = false;
    static CUtensorMap tmX, tmW;
    static const float* x_cached = nullptr;
    if (!init_done || x_cached != x) {
        cudaFuncSetAttribute(gemm_tc_kernel,
                             cudaFuncAttributeMaxDynamicSharedMemorySize, SMEM_SIZE);
        void* p = nullptr;
        cudaDriverEntryPointQueryResult qr;
        if (cudaGetDriverEntryPointByVersion("cuTensorMapEncodeTiled", &p, 12000,
                                             cudaEnableDefault, &qr) != cudaSuccess || !p) {
            cudaGetDriverEntryPoint("cuTensorMapEncodeTiled", &p, cudaEnableDefault, &qr);
        }
        pfn_encode_t fn = (pfn_encode_t)p;
        encode_map_f32(fn, &tmX, (void*)x, NTOK);
        encode_map_f32(fn, &tmW, wt, NEXP * DIM);
        init_done = true;
        x_cached = x;
    }

    transpose_w_kernel<<<dim3(16, 16, NEXP), 256>>>(W, wt);

    // 8 m-halves (cluster pairs along x) x 4 n-tiles x 8 experts = 256 CTAs
    dim3 grid(CAP / 128, DIM / 256, NEXP);
    gemm_tc_kernel<<<grid, 256, SMEM_SIZE>>>(tmX, tmW, x, wt, bias, h);

    layernorm_kernel<<<NTOK, 256>>>(h, gamma, beta, out);
}

// round 17
// speedup vs baseline: 1.6156x; 1.6156x over previous
#include <cuda_runtime.h>
#include <cuda.h>
#include <cuda_bf16.h>
#include <cstdint>

#define NTOK   8192
#define DIM    1024
#define NEXP   8
#define CAP    1024
#define LN_EPS 1e-5f

#if defined(__CUDA_ARCH_FEAT_SM103_ALL) || defined(__CUDA_ARCH_FEAT_SM100_ALL)
#define HAS_TCGEN05 1
#else
#define HAS_TCGEN05 0
#endif

// ---------------- scratch (device globals: no allocation) -------------------
__device__ float g_wt[NEXP * DIM * DIM];   // W transposed: [e][n][k], fp32

// ---------------- PTX helpers (guarded) -------------------------------------
#if HAS_TCGEN05
__device__ __forceinline__ uint32_t smem_u32(const void* p) {
    uint32_t a;
    asm("{ .reg .u64 t; cvta.to.shared.u64 t, %1; cvt.u32.u64 %0, t; }" : "=r"(a) : "l"(p));
    return a;
}
__device__ __forceinline__ uint32_t elect_one_pred() {
    uint32_t p;
    asm volatile("{\n\t.reg .pred p;\n\telect.sync _|p, 0xFFFFFFFF;\n\tselp.b32 %0, 1, 0, p;\n\t}" : "=r"(p));
    return p;
}

#define MBARRIER_INIT(addr, cnt) \
    asm volatile("mbarrier.init.shared.b64 [%0], %1;" :: "r"(addr), "r"(cnt) : "memory")
#define MBARRIER_INVAL(addr) \
    asm volatile("mbarrier.inval.shared.b64 [%0];" :: "r"(addr) : "memory")
#define MBARRIER_EXPECT_TX(addr, bytes) \
    asm volatile("mbarrier.arrive.expect_tx.shared.b64 _, [%0], %1;" :: "r"(addr), "r"(bytes) : "memory")
#define MBARRIER_WAIT_PARITY(addr, par) do {                                        \
    uint32_t _m = (addr), _p = (par), _d;                                           \
    asm volatile("{\n\t.reg .pred p;\n\t"                                           \
        "mbarrier.try_wait.parity.acquire.cta.shared::cta.b64 p, [%1], %2;\n\t"     \
        "selp.b32 %0, 1, 0, p;\n\t}" : "=r"(_d) : "r"(_m), "r"(_p) : "memory");     \
    if (!_d) {                                                                      \
        asm volatile("{\n\t.reg .pred P1;\n\t"                                      \
            "WL_%=:\n\t"                                                            \
            "mbarrier.try_wait.parity.acquire.cta.shared::cta.b64 P1, [%0], %1, 0x989680;\n\t" \
            "@P1 bra.uni WD_%=;\n\tbra.uni WL_%=;\n\tWD_%=:\n\t}"                   \
            :: "r"(_m), "r"(_p) : "memory");                                        \
    } } while (0)

#define TMA_LOAD_2D(smem_addr, map, cx, cy, mbar) \
    asm volatile("cp.async.bulk.tensor.2d.shared::cta.global.tile.mbarrier::complete_tx::bytes " \
        "[%0], [%1, {%2, %3}], [%4];" \
        :: "r"(smem_addr), "l"(map), "r"(cx), "r"(cy), "r"(mbar) : "memory")

#define CLUSTER_SYNC() do { \
    asm volatile("barrier.cluster.arrive.aligned;" ::: "memory"); \
    asm volatile("barrier.cluster.wait.aligned;"   ::: "memory"); } while (0)

// DSMEM store of a packed (sum, sq) pair into target rank's SMEM
#define STS_CLUSTER_B64(local_addr, target_rank, val64) \
    asm volatile("{\n\t.reg .b32 ra;\n\t" \
        "mapa.shared::cluster.u32 ra, %0, %1;\n\t" \
        "st.shared::cluster.u64 [ra], %2;\n\t}" \
        :: "r"(local_addr), "r"(target_rank), "l"(val64) : "memory")

#define TCGEN05_ALLOC(smem_addr, ncols) \
    asm volatile("tcgen05.alloc.cta_group::1.sync.aligned.shared::cta.b32 [%0], %1;" \
                 :: "r"(smem_addr), "r"(ncols) : "memory")
#define TCGEN05_DEALLOC(tmem, ncols) \
    asm volatile("tcgen05.dealloc.cta_group::1.sync.aligned.b32 %0, %1;" :: "r"(tmem), "r"(ncols))
#define TCGEN05_RELINQ() \
    asm volatile("tcgen05.relinquish_alloc_permit.cta_group::1.sync.aligned;")
#define TCGEN05_COMMIT(mbar) \
    asm volatile("tcgen05.commit.cta_group::1.mbarrier::arrive::one.shared::cluster.b64 [%0];" \
                 :: "r"(mbar) : "memory")
#define TCGEN05_FENCE_AFTER() \
    asm volatile("tcgen05.fence::after_thread_sync;" ::: "memory")
#define TCGEN05_FENCE_BEFORE() \
    asm volatile("tcgen05.fence::before_thread_sync;" ::: "memory")
#define TCGEN05_WAIT_LD() \
    asm volatile("tcgen05.wait::ld.sync.aligned;" ::: "memory")

#define TCGEN05_LD_X32(r, tmem_addr) \
    asm volatile("tcgen05.ld.sync.aligned.32x32b.x32.b32 " \
        "{%0, %1, %2, %3, %4, %5, %6, %7, %8, %9, %10, %11, %12, %13, %14, %15, " \
        " %16, %17, %18, %19, %20, %21, %22, %23, %24, %25, %26, %27, %28, %29, %30, %31}, [%32];" \
        : "=r"((r)[0]),  "=r"((r)[1]),  "=r"((r)[2]),  "=r"((r)[3]),  \
          "=r"((r)[4]),  "=r"((r)[5]),  "=r"((r)[6]),  "=r"((r)[7]),  \
          "=r"((r)[8]),  "=r"((r)[9]),  "=r"((r)[10]), "=r"((r)[11]), \
          "=r"((r)[12]), "=r"((r)[13]), "=r"((r)[14]), "=r"((r)[15]), \
          "=r"((r)[16]), "=r"((r)[17]), "=r"((r)[18]), "=r"((r)[19]), \
          "=r"((r)[20]), "=r"((r)[21]), "=r"((r)[22]), "=r"((r)[23]), \
          "=r"((r)[24]), "=r"((r)[25]), "=r"((r)[26]), "=r"((r)[27]), \
          "=r"((r)[28]), "=r"((r)[29]), "=r"((r)[30]), "=r"((r)[31]) \
        : "r"(tmem_addr))

// SS-mode tf32 MMA, cta_group::1, fp32 accumulate in TMEM (K=8 per step)
__device__ __forceinline__ void mma_tf32_ss(uint32_t d_tmem, uint64_t a_desc,
                                            uint64_t b_desc, uint32_t idesc, bool acc) {
    uint32_t en = acc ? 1u : 0u, z = 0u;
    asm volatile("{\n\t.reg .pred p;\n\tsetp.ne.u32 p, %5, 0;\n\t"
        "tcgen05.mma.cta_group::1.kind::tf32 [%0], %1, %2, %3, {%4, %4, %4, %4}, p;\n\t}"
        :: "r"(d_tmem), "l"(a_desc), "l"(b_desc), "r"(idesc), "r"(z), "r"(en) : "memory");
}

// SW64 K-major descriptor (layout=4, version=1, SBO=32, LBO=1) — proven R6/R7/R11.
static __device__ __forceinline__ uint64_t make_desc_sw64(uint32_t addr) {
    const uint64_t BASE = (4ull << 61) | (1ull << 46) | (32ull << 32) | (1ull << 16);
    return BASE | ((uint64_t)(addr >> 4) & 0x3FFFull);
}

// idesc: dtype F32 (1<<4), atype TF32 (2<<7), btype TF32 (2<<10), N=256, M=128
#define MMA_IDESC ((1u << 4) | (2u << 7) | (2u << 10) | ((256u / 8) << 17) | ((128u / 16) << 24))
#endif // HAS_TCGEN05

// ---------------------------------------------------------------------------
// W transpose (fp32): 64x64 tile per CTA (R11 version, measured 12.6us).
// ---------------------------------------------------------------------------
__global__ __launch_bounds__(256)
void transpose_w_kernel(const float* __restrict__ W, float* __restrict__ Wt)
{
    __shared__ float t[64][65];
    const int e  = blockIdx.z;
    const int k0 = blockIdx.y * 64;
    const int n0 = blockIdx.x * 64;
    const int tid = threadIdx.x;
    const int rr  = tid >> 4;
    const int c4  = tid & 15;

    const float* Wp = W + (size_t)e * DIM * DIM;
    #pragma unroll
    for (int i = 0; i < 4; ++i) {
        int row = rr + i * 16;
        float4 v = *(const float4*)(Wp + (size_t)(k0 + row) * DIM + n0 + c4 * 4);
        t[row][c4 * 4 + 0] = v.x;
        t[row][c4 * 4 + 1] = v.y;
        t[row][c4 * 4 + 2] = v.z;
        t[row][c4 * 4 + 3] = v.w;
    }
    __syncthreads();

    float* Wtp = Wt + (size_t)e * DIM * DIM;
    #pragma unroll
    for (int i = 0; i < 4; ++i) {
        int n = rr + i * 16;
        float4 v;
        v.x = t[c4 * 4 + 0][n];
        v.y = t[c4 * 4 + 1][n];
        v.z = t[c4 * 4 + 2][n];
        v.w = t[c4 * 4 + 3][n];
        *(float4*)(Wtp + (size_t)(n0 + n) * DIM + k0 + c4 * 4) = v;
    }
}

// ---------------------------------------------------------------------------
// Fused GEMM + bias + ReLU + LayerNorm, single-pass tf32.
//   Tile M=256 x N=256, K_CHUNK=16 (SW64), NSTAGE=6, TMA producer, 128 CTAs.
//   Cluster (4,1,1) along n-tiles: the 4 CTAs of one (m,e) tile exchange
//   per-row (sum, sumsq) partials via DSMEM, then apply LN and write d_out.
// ---------------------------------------------------------------------------
#define NSTAGE      6
#define K_CHUNK     16
#define N_CHUNKS    64               // 1024 / 16
#define STAGE_BYTES 32768            // A 16K (256r x 64B) + B 16K (256r x 64B)
#define ST_A 0
#define ST_B 16384
#define OFF_BIAS  (NSTAGE * STAGE_BYTES)       // 196608, 1KB
#define OFF_GAMMA (OFF_BIAS + 1024)            // 1KB
#define OFF_BETA  (OFF_GAMMA + 1024)           // 1KB
#define OFF_PART  (OFF_BETA + 1024)            // 4 slots x 256 rows x 8B = 8KB
#define OFF_TPTR  (OFF_PART + 8192)            // 16B
#define OFF_FULL  (OFF_TPTR + 16)              // 6 x 8B
#define OFF_EMPTY (OFF_FULL + 48)              // 6 x 8B
#define OFF_FINAL (OFF_EMPTY + 48)
#define SMEM_SIZE (OFF_FINAL + 16)

__global__ __launch_bounds__(256, 1) __cluster_dims__(4, 1, 1)
void gemm_tc_kernel(const __grid_constant__ CUtensorMap tmX,
                    const __grid_constant__ CUtensorMap tmW,
                    const float* __restrict__ X,
                    const float* __restrict__ Wt,
                    const float* __restrict__ bias,
                    const float* __restrict__ gamma,
                    const float* __restrict__ beta,
                    float* __restrict__ out)
{
#if HAS_TCGEN05
    extern __shared__ __align__(1024) char smem[];
    const uint32_t sbase  = smem_u32(smem);
    const int e      = blockIdx.z;
    const int rank   = blockIdx.x;              // 0..3 = n-tile = cluster rank
    const int tile_n = rank * 256;
    const int tile_m = blockIdx.y * 256;
    const int tid    = threadIdx.x;
    const int wid    = tid >> 5;
    const int lid    = tid & 31;

    if (wid == 0) {
        TCGEN05_ALLOC(sbase + OFF_TPTR, 512);
        TCGEN05_RELINQ();
    }
    if (tid == 0) {
        #pragma unroll
        for (int s = 0; s < NSTAGE; ++s) {
            MBARRIER_INIT(sbase + OFF_FULL  + s * 8, 1);   // expect_tx by tid0
            MBARRIER_INIT(sbase + OFF_EMPTY + s * 8, 1);   // one commit
        }
        MBARRIER_INIT(sbase + OFF_FINAL, 1);
    }
    ((float*)(smem + OFF_BIAS))[tid]  = bias [e * DIM + tile_n + tid];
    ((float*)(smem + OFF_GAMMA))[tid] = gamma[e * DIM + tile_n + tid];
    ((float*)(smem + OFF_BETA))[tid]  = beta [e * DIM + tile_n + tid];
    __syncthreads();
    uint32_t tmem;
    asm volatile("ld.shared.b32 %0, [%1];" : "=r"(tmem) : "r"(sbase + OFF_TPTR));

    if (tid == 0) {
        // ------- producer: 2 TMA issues per chunk (A 256 rows, B 256 rows)
        const int rowA = e * CAP + tile_m;
        const int rowB = e * DIM + tile_n;
        int st = 0, it = 0;
        for (int c = 0; c < N_CHUNKS; ++c) {
            if (c >= NSTAGE)
                MBARRIER_WAIT_PARITY(sbase + OFF_EMPTY + st * 8, (it - 1) & 1);
            const uint32_t bb = sbase + st * STAGE_BYTES;
            const uint32_t fb = sbase + OFF_FULL + st * 8;
            const int cx = c * K_CHUNK;
            MBARRIER_EXPECT_TX(fb, STAGE_BYTES);
            TMA_LOAD_2D(bb + ST_A, &tmX, cx, rowA, fb);
            TMA_LOAD_2D(bb + ST_B, &tmW, cx, rowB, fb);
            if (++st == NSTAGE) { st = 0; ++it; }
        }
    } else if (wid == 1) {
        // ---------------- MMA warp (single elected thread)
        if (elect_one_pred()) {
            int st = 0, it = 0;
            for (int c = 0; c < N_CHUNKS; ++c) {
                MBARRIER_WAIT_PARITY(sbase + OFF_FULL + st * 8, it & 1);
                const uint32_t bb = sbase + st * STAGE_BYTES;
                uint64_t dA = make_desc_sw64(bb + ST_A);
                uint64_t dB = make_desc_sw64(bb + ST_B);
                #pragma unroll
                for (int h = 0; h < 2; ++h) {                 // M halves
                    const uint32_t D   = tmem + h * 256;
                    const uint64_t hof = h * 512;             // 128 rows x 64B
                    #pragma unroll
                    for (int kk = 0; kk < 2; ++kk)            // K=8 steps
                        mma_tf32_ss(D, dA + hof + kk * 2, dB + kk * 2, MMA_IDESC,
                                    !(c == 0 && kk == 0));
                }
                TCGEN05_COMMIT(sbase + OFF_EMPTY + st * 8);
                if (++st == NSTAGE) { st = 0; ++it; }
            }
            TCGEN05_COMMIT(sbase + OFF_FINAL);
        }
    }

    // ---------------- fused epilogue: bias+ReLU -> row stats -> DSMEM
    //                  exchange -> LayerNorm -> store d_out
    MBARRIER_WAIT_PARITY(sbase + OFF_FINAL, 0);
    TCGEN05_FENCE_AFTER();

    {
        const int half = wid >> 2, sub = wid & 3;
        const int rloc = half * 128 + sub * 32 + lid;       // 0..255 row in tile
        const uint32_t dbase = tmem + half * 256;
        const float* bs = (const float*)(smem + OFF_BIAS);

        // pass 1: per-row partial sums over this CTA's 256 columns
        float s = 0.f, q = 0.f;
        #pragma unroll
        for (int base = 0; base < 256; base += 32) {
            uint32_t r[32];
            TCGEN05_LD_X32(r, dbase + base);
            TCGEN05_WAIT_LD();
            #pragma unroll
            for (int i = 0; i < 32; ++i) {
                float v = fmaxf(__uint_as_float(r[i]) + bs[base + i], 0.f);
                s += v;
                q += v * v;
            }
        }
        // broadcast my (s,q) into slot[rank] of all 4 cluster CTAs
        uint64_t pk;
        asm("mov.b64 %0, {%1, %2};" : "=l"(pk) : "f"(s), "f"(q));
        const uint32_t paddr = sbase + OFF_PART + rank * 2048 + rloc * 8;
        #pragma unroll
        for (int t = 0; t < 4; ++t)
            STS_CLUSTER_B64(paddr, t, pk);
        CLUSTER_SYNC();                                     // release/acquire partials

        // combine: total over all 1024 columns
        float ts = 0.f, tq = 0.f;
        #pragma unroll
        for (int sl = 0; sl < 4; ++sl) {
            float2 p = *(const float2*)(smem + OFF_PART + sl * 2048 + rloc * 8);
            ts += p.x;
            tq += p.y;
        }
        const float mean = ts * (1.f / DIM);
        const float var  = tq * (1.f / DIM) - mean * mean;
        const float rstd = rsqrtf(var + LN_EPS);

        // pass 2: re-read TMEM, apply LN + gamma/beta, store d_out
        const float* gs  = (const float*)(smem + OFF_GAMMA);
        const float* bts = (const float*)(smem + OFF_BETA);
        float* outp = out + (size_t)(e * CAP + tile_m + rloc) * DIM + tile_n;
        #pragma unroll
        for (int base = 0; base < 256; base += 32) {
            uint32_t r[32];
            TCGEN05_LD_X32(r, dbase + base);
            TCGEN05_WAIT_LD();
            float v[32];
            #pragma unroll
            for (int i = 0; i < 32; ++i) {
                float hv = fmaxf(__uint_as_float(r[i]) + bs[base + i], 0.f);
                v[i] = (hv - mean) * rstd * gs[base + i] + bts[base + i];
            }
            #pragma unroll
            for (int qd = 0; qd < 8; ++qd)
                *(float4*)(outp + base + qd * 4) = *(float4*)&v[qd * 4];
        }
        TCGEN05_FENCE_BEFORE();
    }
    __syncthreads();
    if (tid == 0) {
        #pragma unroll
        for (int s = 0; s < NSTAGE; ++s) {
            MBARRIER_INVAL(sbase + OFF_FULL  + s * 8);
            MBARRIER_INVAL(sbase + OFF_EMPTY + s * 8);
        }
        MBARRIER_INVAL(sbase + OFF_FINAL);
    }
    __syncthreads();
    if (wid == 0) TCGEN05_DEALLOC(tmem, 512);
    CLUSTER_SYNC();     // no CTA exits while peers may still read partials

#else
    // --------- correct (slow) fallback: only rank-0 n-tile CTA does full rows
    if (blockIdx.x != 0) return;
    const int e      = blockIdx.z;
    const int tile_m = blockIdx.y * 256;
    const int tid    = threadIdx.x;
    const int row    = tile_m + tid;             // 256 threads = 256 rows
    const float* Ap = X + (size_t)(e * CAP + row) * DIM;
    float hrow[DIM / 256];                        // placeholder to keep code simple
    (void)hrow;
    float s = 0.f, q = 0.f;
    for (int n = 0; n < DIM; ++n) {
        const float* Bp = Wt + ((size_t)e * DIM + n) * DIM;
        float acc = 0.f;
        for (int k = 0; k < DIM; ++k) acc = fmaf(Ap[k], Bp[k], acc);
        acc = fmaxf(acc + bias[e * DIM + n], 0.f);
        s += acc; q += acc * acc;
        out[(size_t)(e * CAP + row) * DIM + n] = acc;   // stash h temporarily
    }
    const float mean = s / DIM;
    const float rstd = rsqrtf(q / DIM - mean * mean + LN_EPS);
    for (int n = 0; n < DIM; ++n) {
        float hv = out[(size_t)(e * CAP + row) * DIM + n];
        out[(size_t)(e * CAP + row) * DIM + n] =
            (hv - mean) * rstd * gamma[e * DIM + n] + beta[e * DIM + n];
    }
#endif
}

// ---------------------------------------------------------------------------
typedef CUresult (CUDAAPI *pfn_encode_t)(
    CUtensorMap*, CUtensorMapDataType, cuuint32_t, void*,
    const cuuint64_t*, const cuuint64_t*, const cuuint32_t*, const cuuint32_t*,
    CUtensorMapInterleave, CUtensorMapSwizzle, CUtensorMapL2promotion,
    CUtensorMapFloatOOBfill);

static void encode_map_f32(pfn_encode_t fn, CUtensorMap* tm, void* ptr, int nrows)
{
    cuuint64_t dims[2]    = {(cuuint64_t)DIM, (cuuint64_t)nrows};
    cuuint64_t strides[1] = {(cuuint64_t)(DIM * 4)};   // bytes per row (f32)
    cuuint32_t box[2]     = {16, 256};                 // 64B x 256 rows, SW64
    cuuint32_t estr[2]    = {1, 1};
    fn(tm, CU_TENSOR_MAP_DATA_TYPE_FLOAT32, 2, ptr, dims, strides, box, estr,
       CU_TENSOR_MAP_INTERLEAVE_NONE, CU_TENSOR_MAP_SWIZZLE_64B,
       CU_TENSOR_MAP_L2_PROMOTION_L2_128B, CU_TENSOR_MAP_FLOAT_OOB_FILL_NONE);
}

extern "C" void kernel_launch(void* const* d_in, const int* in_sizes, int n_in,
                              void* d_out, int out_size)
{
    const float* x     = (const float*)d_in[0];
    // d_in[1] = expert_frequency (equal capacities) — unused
    const float* W     = (const float*)d_in[2];
    const float* bias  = (const float*)d_in[3];
    const float* gamma = (const float*)d_in[4];
    const float* beta  = (const float*)d_in[5];
    float*       out   = (float*)d_out;

    float* wt;
    cudaGetSymbolAddress((void**)&wt, g_wt);

    static bool init_done = false;
    static CUtensorMap tmX, tmW;
    static const float* x_cached = nullptr;
    if (!init_done || x_cached != x) {
        cudaFuncSetAttribute(gemm_tc_kernel,
                             cudaFuncAttributeMaxDynamicSharedMemorySize, SMEM_SIZE);
        void* p = nullptr;
        cudaDriverEntryPointQueryResult qr;
        if (cudaGetDriverEntryPointByVersion("cuTensorMapEncodeTiled", &p, 12000,
                                             cudaEnableDefault, &qr) != cudaSuccess || !p) {
            cudaGetDriverEntryPoint("cuTensorMapEncodeTiled", &p, cudaEnableDefault, &qr);
        }
        pfn_encode_t fn = (pfn_encode_t)p;
        encode_map_f32(fn, &tmX, (void*)x, NTOK);
        encode_map_f32(fn, &tmW, wt, NEXP * DIM);
        init_done = true;
        x_cached = x;
    }

    transpose_w_kernel<<<dim3(16, 16, NEXP), 256>>>(W, wt);

    // 4 n-tiles (cluster) x 4 m-tiles x 8 experts = 128 CTAs, 1 wave
    dim3 grid(DIM / 256, CAP / 256, NEXP);
    gemm_tc_kernel<<<grid, 256, SMEM_SIZE>>>(tmX, tmW, x, wt, bias, gamma, beta, out);
}